// round 4
// baseline (speedup 1.0000x reference)
#include <cuda_runtime.h>

#define TPB    128
#define NBINS  15
#define NCLS   16
#define NCELLS (NBINS * NCLS)   // 240
#define NBLK   912              // 152 SMs * 6 blocks = exactly one wave

// Per-block per-cell partials, [cell][block] so the tail reads rows contiguously.
__device__ float        g_partials[NCELLS * NBLK];
__device__ unsigned int g_ticket = 0;

__device__ __forceinline__ void proc4(float4 xv, float4 tv,
                                      float (*acc)[NBINS][TPB], int tid) {
    float p0 = __fdividef(1.0f, 1.0f + __expf(-xv.x));
    float p1 = __fdividef(1.0f, 1.0f + __expf(-xv.y));
    float p2 = __fdividef(1.0f, 1.0f + __expf(-xv.z));
    float p3 = __fdividef(1.0f, 1.0f + __expf(-xv.w));
    int b0 = (int)(p0 * 15.0f); b0 = b0 > 14 ? 14 : b0;
    int b1 = (int)(p1 * 15.0f); b1 = b1 > 14 ? 14 : b1;
    int b2 = (int)(p2 * 15.0f); b2 = b2 > 14 ? 14 : b2;
    int b3 = (int)(p3 * 15.0f); b3 = b3 > 14 ? 14 : b3;
    acc[0][b0][tid] += p0 - tv.x;
    acc[1][b1][tid] += p1 - tv.y;
    acc[2][b2][tid] += p2 - tv.z;
    acc[3][b3][tid] += p3 - tv.w;
}

__global__ void __launch_bounds__(TPB, 6)
ece_fused(const float4* __restrict__ x4, const float4* __restrict__ t4, int n4,
          float* __restrict__ out, float inv_scale) {
    // acc[j][bin][tid]: j = element index within the float4. Thread's class set
    // is {4*(tid&3)+j}: loop-invariant since the grid stride is a multiple of 4.
    // Bank = tid mod 32 regardless of bin/plane -> conflict-free LDS/STS.
    __shared__ float acc[4][NBINS][TPB];
    const int tid = threadIdx.x;
    #pragma unroll
    for (int b = 0; b < NBINS; b++) {
        acc[0][b][tid] = 0.0f; acc[1][b][tid] = 0.0f;
        acc[2][b][tid] = 0.0f; acc[3][b][tid] = 0.0f;
    }
    __syncthreads();

    const int stride = NBLK * TPB;
    int i = blockIdx.x * TPB + tid;

    for (; i + stride < n4; i += 2 * stride) {
        float4 x0 = __ldcs(&x4[i]);
        float4 x1 = __ldcs(&x4[i + stride]);
        float4 t0 = __ldcs(&t4[i]);
        float4 t1 = __ldcs(&t4[i + stride]);
        proc4(x0, t0, acc, tid);
        proc4(x1, t1, acc, tid);
    }
    for (; i < n4; i += stride) {
        float4 x = __ldcs(&x4[i]);
        float4 t = __ldcs(&t4[i]);
        proc4(x, t, acc, tid);
    }
    __syncthreads();

    // Fold 4*128 private slots into 240 cells; each thread does <=2 cells.
    // Cell (b, c) with c = 4q+j lives in plane j, slots tid = 4m+q.
    for (int cell = tid; cell < NCELLS; cell += TPB) {
        int b = cell >> 4;
        int c = cell & 15;
        int q = c >> 2;
        int j = c & 3;
        float s = 0.0f;
        #pragma unroll
        for (int m = 0; m < TPB / 4; m++) s += acc[j][b][4 * m + q];
        g_partials[cell * NBLK + blockIdx.x] = s;
    }

    // Last-block tail: reduce all partials in-kernel (L2-hot), write scalar.
    __threadfence();
    __shared__ bool isLast;
    if (tid == 0)
        isLast = (atomicAdd(&g_ticket, 1u) == (unsigned)(NBLK - 1));
    __syncthreads();
    if (!isLast) return;

    __shared__ float warp_tot[4];
    const int warp = tid >> 5;
    const int lane = tid & 31;
    float total = 0.0f;
    for (int cell = warp; cell < NCELLS; cell += 4) {
        const float4* row = (const float4*)&g_partials[cell * NBLK];  // 228 float4
        float s0 = 0.0f, s1 = 0.0f, s2 = 0.0f, s3 = 0.0f;
        #pragma unroll
        for (int k = lane; k < NBLK / 4; k += 32) {
            float4 v = row[k];
            s0 += v.x; s1 += v.y; s2 += v.z; s3 += v.w;
        }
        float s = (s0 + s1) + (s2 + s3);
        #pragma unroll
        for (int off = 16; off > 0; off >>= 1)
            s += __shfl_xor_sync(0xffffffffu, s, off);
        if (lane == 0) total += fabsf(s);
    }
    if (lane == 0) warp_tot[warp] = total;
    __syncthreads();
    if (tid == 0) {
        out[0] = (warp_tot[0] + warp_tot[1] + warp_tot[2] + warp_tot[3]) * inv_scale;
        g_ticket = 0;   // reset for next graph replay
    }
}

extern "C" void kernel_launch(void* const* d_in, const int* in_sizes, int n_in,
                              void* d_out, int out_size) {
    const float4* x4 = (const float4*)d_in[0];
    const float4* t4 = (const float4*)d_in[1];
    float* out = (float*)d_out;
    const int n  = in_sizes[0];            // B*C = 33 554 432
    const int n4 = n >> 2;
    const float B = (float)(n / NCLS);

    // ECE = (sum over 240 cells of |sum(p - t)|) / B / NCELLS  (all nonempty)
    ece_fused<<<NBLK, TPB>>>(x4, t4, n4, out, 1.0f / (B * (float)NCELLS));
}